// round 12
// baseline (speedup 1.0000x reference)
#include <cuda_runtime.h>
#include <math.h>

#define BB 16
#define NN 16384
#define NCHUNK (NN / 32)        // 512
#define NGROUP (NCHUNK / 4)     // 128 groups of 4 chunks

// ---------------------------------------------------------------------------
// Single fused kernel. One block = 3 warps per batch row.
//   warp 0 (compute): the round-9 minimal recurrence loop (unchanged):
//     y[n] = x[n] + sum_j blk[j]*y[n-zc-j], delays in [37,103];
//     SMEM ring 256 + 7-slot mirror, pre-zeroed (zero init state for free),
//     branchless immediate-offset 7-tap LDS, __syncwarp per chunk, group g+1
//     coefficients preloaded at the end of iteration g.
//   warps 1,2 (helpers): replace BOTH the old coef_kernel and the cp.async
//     stream. Per group iteration g:
//       - compute coefficients for group g+2 from inputs held in registers
//         (LDG'd during iteration g-1 -> full iteration of latency cover)
//         and STS into stage ((g+2)&3)*4 of the 16-stage buffer;
//       - LDG raw inputs (f0, x, l_b) for group g+3 into registers;
//       - warp 1 additionally copies group g-1's ring slots to gmem;
//       - __syncthreads (publishes stage writes + ring STS both ways).
//   Coefficient math (identical to the old pass 1):
//     g = 0.99*lb0, p = lb1, b0 = g(1-p), a1 = g*p
//     f0c = f0 - a1/(b0+a1+1e-7); zc = floor(f0c)-2; alpha = f0c - zc
//     Lagrange-5 weights via prefix/suffix products;
//     blk[0]=b0*w0; blk[j]=b0*w[j]+a1*w[j-1]; blk[6]=a1*w5; B.w = x[n];
//     lo = (n - zc - 6) & 255  (ring slot of the 7-tap window start).
// ---------------------------------------------------------------------------
struct SmemCoef {
    float4 A[16][32];
    float4 B[16][32];
    int    I[16][32];
};

__device__ __forceinline__ void coef_one(float f0v, float xv, float gg, float pp,
                                         int n, float4& A, float4& B, int& lo)
{
    float g  = 0.99f * gg;
    float b0 = g * (1.0f - pp);
    float a1 = g * pp;
    float f0c = f0v - a1 / (b0 + a1 + 1e-7f);

    int   zc    = (int)floorf(f0c) - 2;     // in [37, 97]
    float alpha = f0c - (float)zc;          // in [2, 3)

    float u0 = alpha;
    float u1 = alpha - 1.0f;
    float u2 = alpha - 2.0f;
    float u3 = alpha - 3.0f;
    float u4 = alpha - 4.0f;
    float u5 = alpha - 5.0f;

    float pre1 = u0;
    float pre2 = pre1 * u1;
    float pre3 = pre2 * u2;
    float pre4 = pre3 * u3;
    float pre5 = pre4 * u4;
    float suf4 = u5;
    float suf3 = suf4 * u4;
    float suf2 = suf3 * u3;
    float suf1 = suf2 * u2;
    float suf0 = suf1 * u1;

    float w0 = suf0        * (-1.0f / 120.0f);
    float w1 = pre1 * suf1 * ( 1.0f /  24.0f);
    float w2 = pre2 * suf2 * (-1.0f /  12.0f);
    float w3 = pre3 * suf3 * ( 1.0f /  12.0f);
    float w4 = pre4 * suf4 * (-1.0f /  24.0f);
    float w5 = pre5        * ( 1.0f / 120.0f);

    A = make_float4(b0 * w0,
                    fmaf(b0, w1, a1 * w0),
                    fmaf(b0, w2, a1 * w1),
                    fmaf(b0, w3, a1 * w2));
    B = make_float4(fmaf(b0, w4, a1 * w3),
                    fmaf(b0, w5, a1 * w4),
                    a1 * w5,
                    xv);
    lo = (n - zc - 6) & 255;
}

__global__ void __launch_bounds__(96, 1)
lpc_kernel(const float* __restrict__ f0,
           const float* __restrict__ x,
           const float* __restrict__ lb,
           float* __restrict__ out)
{
    __shared__ SmemCoef sc;
    __shared__ float ring[264];

    const int b    = blockIdx.x;
    const int tid  = threadIdx.x;
    const int wid  = tid >> 5;
    const int lane = tid & 31;
    const float*  __restrict__ f0r = f0 + b * NN;
    const float*  __restrict__ xr  = x  + b * NN;
    const float2* __restrict__ lbr = reinterpret_cast<const float2*>(lb) + b * NN;
    float* __restrict__ outr = out + b * NN;

    // helper-warp input registers (group being carried toward compute)
    float  cf0a, cxa, cf0b, cxb;
    float2 cgpa, cgpb;
    int h = 0, c1 = 0, c2 = 0;

    if (wid == 0) {
        // zero the ring (implements zero initial state via wrap mapping)
#pragma unroll
        for (int k = 0; k < 8; k++) ring[lane + 32 * k] = 0.0f;
        if (lane < 8) ring[256 + lane] = 0.0f;
    } else {
        h  = (wid - 1) * 32 + lane;       // 0..63: sample offset within group
        c1 = wid - 1;                     // chunk for sample h      (0 or 1)
        c2 = wid + 1;                     // chunk for sample h+64   (2 or 3)

        // prologue: LDG inputs for groups 0,1,2 (all issued up front)
        float  f0_0a = f0r[h],        x_0a = xr[h];
        float2 gp_0a = lbr[h];
        float  f0_0b = f0r[h + 64],   x_0b = xr[h + 64];
        float2 gp_0b = lbr[h + 64];
        float  f0_1a = f0r[128 + h],      x_1a = xr[128 + h];
        float2 gp_1a = lbr[128 + h];
        float  f0_1b = f0r[128 + h + 64], x_1b = xr[128 + h + 64];
        float2 gp_1b = lbr[128 + h + 64];
        cf0a = f0r[256 + h];       cxa = xr[256 + h];       cgpa = lbr[256 + h];
        cf0b = f0r[256 + h + 64];  cxb = xr[256 + h + 64];  cgpb = lbr[256 + h + 64];

        float4 A, B; int lo;
        // group 0 -> stages 0..3
        coef_one(f0_0a, x_0a, gp_0a.x, gp_0a.y, h, A, B, lo);
        sc.A[c1][lane] = A; sc.B[c1][lane] = B; sc.I[c1][lane] = lo;
        coef_one(f0_0b, x_0b, gp_0b.x, gp_0b.y, h + 64, A, B, lo);
        sc.A[c2][lane] = A; sc.B[c2][lane] = B; sc.I[c2][lane] = lo;
        // group 1 -> stages 4..7
        coef_one(f0_1a, x_1a, gp_1a.x, gp_1a.y, 128 + h, A, B, lo);
        sc.A[4 + c1][lane] = A; sc.B[4 + c1][lane] = B; sc.I[4 + c1][lane] = lo;
        coef_one(f0_1b, x_1b, gp_1b.x, gp_1b.y, 128 + h + 64, A, B, lo);
        sc.A[4 + c2][lane] = A; sc.B[4 + c2][lane] = B; sc.I[4 + c2][lane] = lo;
    }
    __syncthreads();

    if (wid == 0) {
        // ---------------- compute warp (round-9 loop, unchanged) ----------------
        const bool lane_lt7 = lane < 7;

        float4 A0 = sc.A[0][lane], B0 = sc.B[0][lane];
        float4 A1 = sc.A[1][lane], B1 = sc.B[1][lane];
        float4 A2 = sc.A[2][lane], B2 = sc.B[2][lane];
        float4 A3 = sc.A[3][lane], B3 = sc.B[3][lane];
        int l0 = sc.I[0][lane];
        int l1 = sc.I[1][lane];
        int l2 = sc.I[2][lane];
        int l3 = sc.I[3][lane];

        for (int g = 0; g < NGROUP; g++) {
            const int wb = (g & 1) * 128;           // ring write base
            const bool mir = ((g & 1) == 0) && lane_lt7;

            // ---- chunk 0 (ordered by the group barrier) ----
            {
                const float* w = ring + l0;
                float v6 = w[0], v5 = w[1], v4 = w[2], v3 = w[3];
                float v2 = w[4], v1 = w[5], v0 = w[6];
                float t0 = fmaf(A0.x, v0, B0.w);
                float t1 = fmaf(A0.z, v2, A0.y * v1);
                float t2 = fmaf(B0.x, v4, A0.w * v3);
                float t3 = fmaf(B0.z, v6, B0.y * v5);
                float acc = (t0 + t1) + (t2 + t3);
                ring[wb + lane] = acc;
                if (mir) ring[256 + lane] = acc;
            }
            __syncwarp();
            // ---- chunk 1 ----
            {
                const float* w = ring + l1;
                float v6 = w[0], v5 = w[1], v4 = w[2], v3 = w[3];
                float v2 = w[4], v1 = w[5], v0 = w[6];
                float t0 = fmaf(A1.x, v0, B1.w);
                float t1 = fmaf(A1.z, v2, A1.y * v1);
                float t2 = fmaf(B1.x, v4, A1.w * v3);
                float t3 = fmaf(B1.z, v6, B1.y * v5);
                ring[wb + 32 + lane] = (t0 + t1) + (t2 + t3);
            }
            __syncwarp();
            // ---- chunk 2 ----
            {
                const float* w = ring + l2;
                float v6 = w[0], v5 = w[1], v4 = w[2], v3 = w[3];
                float v2 = w[4], v1 = w[5], v0 = w[6];
                float t0 = fmaf(A2.x, v0, B2.w);
                float t1 = fmaf(A2.z, v2, A2.y * v1);
                float t2 = fmaf(B2.x, v4, A2.w * v3);
                float t3 = fmaf(B2.z, v6, B2.y * v5);
                ring[wb + 64 + lane] = (t0 + t1) + (t2 + t3);
            }
            __syncwarp();
            // ---- chunk 3 ----
            {
                const float* w = ring + l3;
                float v6 = w[0], v5 = w[1], v4 = w[2], v3 = w[3];
                float v2 = w[4], v1 = w[5], v0 = w[6];
                float t0 = fmaf(A3.x, v0, B3.w);
                float t1 = fmaf(A3.z, v2, A3.y * v1);
                float t2 = fmaf(B3.x, v4, A3.w * v3);
                float t3 = fmaf(B3.z, v6, B3.y * v5);
                ring[wb + 96 + lane] = (t0 + t1) + (t2 + t3);
            }

            // preload group g+1 coefficients (stage written >=1 barrier ago)
            const int st = ((g + 1) & 3) * 4;
            A0 = sc.A[st + 0][lane]; B0 = sc.B[st + 0][lane];
            A1 = sc.A[st + 1][lane]; B1 = sc.B[st + 1][lane];
            A2 = sc.A[st + 2][lane]; B2 = sc.B[st + 2][lane];
            A3 = sc.A[st + 3][lane]; B3 = sc.B[st + 3][lane];
            l0 = sc.I[st + 0][lane];
            l1 = sc.I[st + 1][lane];
            l2 = sc.I[st + 2][lane];
            l3 = sc.I[st + 3][lane];

            __syncthreads();                        // group boundary
        }
    } else {
        // ---------------- helper warps ----------------
        for (int g = 0; g < NGROUP; g++) {
            if (g + 2 < NGROUP) {                   // coefs for group g+2
                const int st = ((g + 2) & 3) * 4;
                const int n1 = (g + 2) * 128 + h;
                float4 A, B; int lo;
                coef_one(cf0a, cxa, cgpa.x, cgpa.y, n1, A, B, lo);
                sc.A[st + c1][lane] = A; sc.B[st + c1][lane] = B; sc.I[st + c1][lane] = lo;
                coef_one(cf0b, cxb, cgpb.x, cgpb.y, n1 + 64, A, B, lo);
                sc.A[st + c2][lane] = A; sc.B[st + c2][lane] = B; sc.I[st + c2][lane] = lo;
            }
            if (g + 3 < NGROUP) {                   // LDG inputs for group g+3
                const int s = (g + 3) * 128 + h;
                cf0a = f0r[s];      cxa = xr[s];      cgpa = lbr[s];
                cf0b = f0r[s + 64]; cxb = xr[s + 64]; cgpb = lbr[s + 64];
            }
            if (wid == 1 && g >= 1) {               // copy group g-1 -> gmem
                const int rb = ((g - 1) & 1) * 128;
                float* o = outr + (g - 1) * 128 + lane;
#pragma unroll
                for (int k = 0; k < 4; k++)
                    o[k * 32] = ring[rb + k * 32 + lane];
            }
            __syncthreads();
        }
        // final group's output (last __syncthreads drained compute's STS)
        if (wid == 1) {
            const int rb = ((NGROUP - 1) & 1) * 128;
            float* o = outr + (NGROUP - 1) * 128 + lane;
#pragma unroll
            for (int k = 0; k < 4; k++)
                o[k * 32] = ring[rb + k * 32 + lane];
        }
    }
}

// ---------------------------------------------------------------------------
// Inputs (metadata order): f0 [B,N] f32, x [B,N] f32, l_b [B,N,2] f32, K int32
// Output: y [B,N] f32
// ---------------------------------------------------------------------------
extern "C" void kernel_launch(void* const* d_in, const int* in_sizes, int n_in,
                              void* d_out, int out_size)
{
    const float* f0 = (const float*)d_in[0];
    const float* x  = (const float*)d_in[1];
    const float* lb = (const float*)d_in[2];
    float* out = (float*)d_out;

    lpc_kernel<<<BB, 96>>>(f0, x, lb, out);
}

// round 13
// speedup vs baseline: 1.2800x; 1.2800x over previous
#include <cuda_runtime.h>
#include <math.h>

#define BB 16
#define NN 16384
#define NCHUNK (NN / 32)        // 512
#define NGROUP (NCHUNK / 4)     // 128 groups of 4 chunks

// ---------------------------------------------------------------------------
// Single fused kernel. One block = 5 warps per batch row (160 threads).
//   wid 4 (compute, highest wid => arbiter priority on its SMSP):
//     round-9 minimal recurrence loop, unchanged:
//     y[n] = x[n] + sum_j blk[j]*y[n-zc-j], delays in [37,103];
//     SMEM ring 256 + 7-slot mirror, pre-zeroed (zero init state free),
//     branchless immediate-offset 7-tap LDS, __syncwarp per chunk, group g+1
//     coefficients preloaded at the end of iteration g.
//   wids 0..3 (helpers): helper warp w owns chunk w of every group —
//     ONE coef_one per lane per group:
//       - iteration g: compute coefficients for group g+2 from inputs held
//         in registers (LDG'd during iteration g-1) and STS into stage
//         ((g+2)&3)*4 + w of the 16-stage buffer;
//       - LDG raw inputs (f0, x, l_b) for group g+3;
//       - wid 1 additionally copies group g-1's ring slots to gmem;
//       - __syncthreads (publishes stage writes + ring STS both ways).
//   Coefficient math identical to the original pass 1.
// ---------------------------------------------------------------------------
struct SmemCoef {
    float4 A[16][32];
    float4 B[16][32];
    int    I[16][32];
};

__device__ __forceinline__ void coef_one(float f0v, float xv, float gg, float pp,
                                         int n, float4& A, float4& B, int& lo)
{
    float g  = 0.99f * gg;
    float b0 = g * (1.0f - pp);
    float a1 = g * pp;
    float f0c = f0v - a1 / (b0 + a1 + 1e-7f);

    int   zc    = (int)floorf(f0c) - 2;     // in [37, 97]
    float alpha = f0c - (float)zc;          // in [2, 3)

    float u0 = alpha;
    float u1 = alpha - 1.0f;
    float u2 = alpha - 2.0f;
    float u3 = alpha - 3.0f;
    float u4 = alpha - 4.0f;
    float u5 = alpha - 5.0f;

    float pre1 = u0;
    float pre2 = pre1 * u1;
    float pre3 = pre2 * u2;
    float pre4 = pre3 * u3;
    float pre5 = pre4 * u4;
    float suf4 = u5;
    float suf3 = suf4 * u4;
    float suf2 = suf3 * u3;
    float suf1 = suf2 * u2;
    float suf0 = suf1 * u1;

    float w0 = suf0        * (-1.0f / 120.0f);
    float w1 = pre1 * suf1 * ( 1.0f /  24.0f);
    float w2 = pre2 * suf2 * (-1.0f /  12.0f);
    float w3 = pre3 * suf3 * ( 1.0f /  12.0f);
    float w4 = pre4 * suf4 * (-1.0f /  24.0f);
    float w5 = pre5        * ( 1.0f / 120.0f);

    A = make_float4(b0 * w0,
                    fmaf(b0, w1, a1 * w0),
                    fmaf(b0, w2, a1 * w1),
                    fmaf(b0, w3, a1 * w2));
    B = make_float4(fmaf(b0, w4, a1 * w3),
                    fmaf(b0, w5, a1 * w4),
                    a1 * w5,
                    xv);
    lo = (n - zc - 6) & 255;
}

__global__ void __launch_bounds__(160, 1)
lpc_kernel(const float* __restrict__ f0,
           const float* __restrict__ x,
           const float* __restrict__ lb,
           float* __restrict__ out)
{
    __shared__ SmemCoef sc;
    __shared__ float ring[264];

    const int b    = blockIdx.x;
    const int tid  = threadIdx.x;
    const int wid  = tid >> 5;
    const int lane = tid & 31;
    const float*  __restrict__ f0r = f0 + b * NN;
    const float*  __restrict__ xr  = x  + b * NN;
    const float2* __restrict__ lbr = reinterpret_cast<const float2*>(lb) + b * NN;
    float* __restrict__ outr = out + b * NN;

    // helper carried inputs (group g+2 during iteration g)
    float  cf0, cx;
    float2 cgp;
    int h = 0;

    if (wid == 4) {
        // compute warp: zero the ring (zero initial state via wrap mapping)
#pragma unroll
        for (int k = 0; k < 8; k++) ring[lane + 32 * k] = 0.0f;
        if (lane < 8) ring[256 + lane] = 0.0f;
    } else {
        h = wid * 32 + lane;              // sample offset within a group

        // prologue: LDG inputs for groups 0,1,2
        float  f0_0 = f0r[h],       x_0 = xr[h];
        float2 gp_0 = lbr[h];
        float  f0_1 = f0r[128 + h], x_1 = xr[128 + h];
        float2 gp_1 = lbr[128 + h];
        cf0 = f0r[256 + h]; cx = xr[256 + h]; cgp = lbr[256 + h];

        float4 A, B; int lo;
        coef_one(f0_0, x_0, gp_0.x, gp_0.y, h, A, B, lo);          // group 0
        sc.A[wid][lane] = A; sc.B[wid][lane] = B; sc.I[wid][lane] = lo;
        coef_one(f0_1, x_1, gp_1.x, gp_1.y, 128 + h, A, B, lo);    // group 1
        sc.A[4 + wid][lane] = A; sc.B[4 + wid][lane] = B; sc.I[4 + wid][lane] = lo;
    }
    __syncthreads();

    if (wid == 4) {
        // ---------------- compute warp (round-9 loop, unchanged) ------------
        const bool lane_lt7 = lane < 7;

        float4 A0 = sc.A[0][lane], B0 = sc.B[0][lane];
        float4 A1 = sc.A[1][lane], B1 = sc.B[1][lane];
        float4 A2 = sc.A[2][lane], B2 = sc.B[2][lane];
        float4 A3 = sc.A[3][lane], B3 = sc.B[3][lane];
        int l0 = sc.I[0][lane];
        int l1 = sc.I[1][lane];
        int l2 = sc.I[2][lane];
        int l3 = sc.I[3][lane];

        for (int g = 0; g < NGROUP; g++) {
            const int wb = (g & 1) * 128;           // ring write base
            const bool mir = ((g & 1) == 0) && lane_lt7;

            // ---- chunk 0 (ordered by the group barrier) ----
            {
                const float* w = ring + l0;
                float v6 = w[0], v5 = w[1], v4 = w[2], v3 = w[3];
                float v2 = w[4], v1 = w[5], v0 = w[6];
                float t0 = fmaf(A0.x, v0, B0.w);
                float t1 = fmaf(A0.z, v2, A0.y * v1);
                float t2 = fmaf(B0.x, v4, A0.w * v3);
                float t3 = fmaf(B0.z, v6, B0.y * v5);
                float acc = (t0 + t1) + (t2 + t3);
                ring[wb + lane] = acc;
                if (mir) ring[256 + lane] = acc;
            }
            __syncwarp();
            // ---- chunk 1 ----
            {
                const float* w = ring + l1;
                float v6 = w[0], v5 = w[1], v4 = w[2], v3 = w[3];
                float v2 = w[4], v1 = w[5], v0 = w[6];
                float t0 = fmaf(A1.x, v0, B1.w);
                float t1 = fmaf(A1.z, v2, A1.y * v1);
                float t2 = fmaf(B1.x, v4, A1.w * v3);
                float t3 = fmaf(B1.z, v6, B1.y * v5);
                ring[wb + 32 + lane] = (t0 + t1) + (t2 + t3);
            }
            __syncwarp();
            // ---- chunk 2 ----
            {
                const float* w = ring + l2;
                float v6 = w[0], v5 = w[1], v4 = w[2], v3 = w[3];
                float v2 = w[4], v1 = w[5], v0 = w[6];
                float t0 = fmaf(A2.x, v0, B2.w);
                float t1 = fmaf(A2.z, v2, A2.y * v1);
                float t2 = fmaf(B2.x, v4, A2.w * v3);
                float t3 = fmaf(B2.z, v6, B2.y * v5);
                ring[wb + 64 + lane] = (t0 + t1) + (t2 + t3);
            }
            __syncwarp();
            // ---- chunk 3 ----
            {
                const float* w = ring + l3;
                float v6 = w[0], v5 = w[1], v4 = w[2], v3 = w[3];
                float v2 = w[4], v1 = w[5], v0 = w[6];
                float t0 = fmaf(A3.x, v0, B3.w);
                float t1 = fmaf(A3.z, v2, A3.y * v1);
                float t2 = fmaf(B3.x, v4, A3.w * v3);
                float t3 = fmaf(B3.z, v6, B3.y * v5);
                ring[wb + 96 + lane] = (t0 + t1) + (t2 + t3);
            }

            // preload group g+1 coefficients (stage written >=1 barrier ago)
            const int st = ((g + 1) & 3) * 4;
            A0 = sc.A[st + 0][lane]; B0 = sc.B[st + 0][lane];
            A1 = sc.A[st + 1][lane]; B1 = sc.B[st + 1][lane];
            A2 = sc.A[st + 2][lane]; B2 = sc.B[st + 2][lane];
            A3 = sc.A[st + 3][lane]; B3 = sc.B[st + 3][lane];
            l0 = sc.I[st + 0][lane];
            l1 = sc.I[st + 1][lane];
            l2 = sc.I[st + 2][lane];
            l3 = sc.I[st + 3][lane];

            __syncthreads();                        // group boundary
        }
    } else {
        // ---------------- helper warps (wid 0..3) ----------------
        for (int g = 0; g < NGROUP; g++) {
            if (g + 2 < NGROUP) {                   // coefs for group g+2
                const int st = ((g + 2) & 3) * 4 + wid;
                float4 A, B; int lo;
                coef_one(cf0, cx, cgp.x, cgp.y, (g + 2) * 128 + h, A, B, lo);
                sc.A[st][lane] = A; sc.B[st][lane] = B; sc.I[st][lane] = lo;
            }
            if (g + 3 < NGROUP) {                   // LDG inputs for group g+3
                const int s = (g + 3) * 128 + h;
                cf0 = f0r[s]; cx = xr[s]; cgp = lbr[s];
            }
            if (wid == 1 && g >= 1) {               // copy group g-1 -> gmem
                const int rb = ((g - 1) & 1) * 128;
                float* o = outr + (g - 1) * 128 + lane;
#pragma unroll
                for (int k = 0; k < 4; k++)
                    o[k * 32] = ring[rb + k * 32 + lane];
            }
            __syncthreads();
        }
        // final group's output (last __syncthreads drained compute's STS)
        if (wid == 1) {
            const int rb = ((NGROUP - 1) & 1) * 128;
            float* o = outr + (NGROUP - 1) * 128 + lane;
#pragma unroll
            for (int k = 0; k < 4; k++)
                o[k * 32] = ring[rb + k * 32 + lane];
        }
    }
}

// ---------------------------------------------------------------------------
// Inputs (metadata order): f0 [B,N] f32, x [B,N] f32, l_b [B,N,2] f32, K int32
// Output: y [B,N] f32
// ---------------------------------------------------------------------------
extern "C" void kernel_launch(void* const* d_in, const int* in_sizes, int n_in,
                              void* d_out, int out_size)
{
    const float* f0 = (const float*)d_in[0];
    const float* x  = (const float*)d_in[1];
    const float* lb = (const float*)d_in[2];
    float* out = (float*)d_out;

    lpc_kernel<<<BB, 160>>>(f0, x, lb, out);
}